// round 13
// baseline (speedup 1.0000x reference)
#include <cuda_runtime.h>
#include <cuda_fp16.h>

// SinkhornLoss B=8, N=2048, EPS=0.1, 20 iters — persistent-kernel Sinkhorn.
// R13: the 20 iterations run inside ONE kernel (512 co-resident blocks,
// software grid barrier), eliminating 40 launch boundaries. Sweep = R12's
// proven 4-row-stage single-decode structure, stripe widened to 32 rows
// (partials halve to 4 MB); combine runs warm-L2 right after the barrier.

#define BATCH 8
#define NDIM  2048
#define LOGN  11
#define SINK_ITERS 20
#define PSTRIPE   32
#define PNSTRIPES (NDIM / PSTRIPE)      // 64
#define NBLOCKS   (PNSTRIPES * BATCH)   // 512

#define SCALE_EXP 14.426950408889634f   // log2(e)/EPS
#define EPS_LN2   0.06931471805599453f  // EPS*ln(2)

__device__ __half g_K[(size_t)BATCH * NDIM * NDIM];           // 67 MB
__device__ float  g_M[BATCH * NDIM];
__device__ float  g_U[BATCH * NDIM];
__device__ float  g_V[BATCH * NDIM];
__device__ float  g_part[(size_t)BATCH * PNSTRIPES * NDIM];   // 4 MB col partials
__device__ float  g_rowpart[BATCH * NDIM];
__device__ unsigned g_bar_cnt;   // zero-init; self-resets each barrier
__device__ unsigned g_bar_gen;

__device__ __forceinline__ float ex2f(float x) {
    float y; asm("ex2.approx.f32 %0, %1;" : "=f"(y) : "f"(x)); return y;
}
__device__ __forceinline__ float lg2f(float x) {
    float y; asm("lg2.approx.f32 %0, %1;" : "=f"(y) : "f"(x)); return y;
}

__device__ __forceinline__ float block_sum256(float v) {
    __shared__ float sm[8];
    const int lane = threadIdx.x & 31, w = threadIdx.x >> 5;
#pragma unroll
    for (int o = 16; o; o >>= 1) v += __shfl_xor_sync(0xffffffffu, v, o);
    if (lane == 0) sm[w] = v;
    __syncthreads();
    if (w == 0) {
        v = (lane < 8) ? sm[lane] : 0.0f;
#pragma unroll
        for (int o = 4; o; o >>= 1) v += __shfl_xor_sync(0xffffffffu, v, o);
    }
    return v;
}

// Sense-reversing grid barrier for exactly NBLOCKS co-resident blocks.
__device__ __forceinline__ void grid_barrier() {
    __syncthreads();
    if (threadIdx.x == 0) {
        unsigned* cntp = &g_bar_cnt;
        unsigned* genp = &g_bar_gen;
        unsigned my_gen;
        asm volatile("ld.acquire.gpu.global.u32 %0, [%1];"
                     : "=r"(my_gen) : "l"(genp) : "memory");
        __threadfence();   // publish this block's writes (and CCTL.IVALL L1D)
        unsigned arrived;
        asm volatile("atom.release.gpu.global.add.u32 %0, [%1], 1;"
                     : "=r"(arrived) : "l"(cntp) : "memory");
        if (arrived == NBLOCKS - 1) {
            asm volatile("st.relaxed.gpu.global.u32 [%0], %1;"
                         :: "l"(cntp), "r"(0u) : "memory");
            unsigned dummy;
            asm volatile("atom.release.gpu.global.add.u32 %0, [%1], 1;"
                         : "=r"(dummy) : "l"(genp) : "memory");
        } else {
            unsigned g;
            do {
                __nanosleep(128);
                asm volatile("ld.acquire.gpu.global.u32 %0, [%1];"
                             : "=r"(g) : "l"(genp) : "memory");
            } while (g == my_gen);
        }
        __threadfence();   // invalidate L1D so post-barrier loads see peers' data
    }
    __syncthreads();
}

__global__ void init_v_kernel() {
    g_V[blockIdx.x * 256 + threadIdx.x] = 1.0f;
}

// One block per row: row min, then K'16 = exp2((m - d)*SCALE_EXP).
__global__ void precompute_kernel(const float* __restrict__ D) {
    const int row = blockIdx.x;
    const float4* __restrict__ Dr = (const float4*)(D + (size_t)row * NDIM);
    float4 a = Dr[2 * threadIdx.x];
    float4 b = Dr[2 * threadIdx.x + 1];
    float mn = fminf(fminf(fminf(a.x, a.y), fminf(a.z, a.w)),
                     fminf(fminf(b.x, b.y), fminf(b.z, b.w)));
    __shared__ float sm[8];
    __shared__ float smin;
    const int lane = threadIdx.x & 31, w = threadIdx.x >> 5;
#pragma unroll
    for (int o = 16; o; o >>= 1) mn = fminf(mn, __shfl_xor_sync(0xffffffffu, mn, o));
    if (lane == 0) sm[w] = mn;
    __syncthreads();
    if (threadIdx.x == 0) {
        float m = sm[0];
#pragma unroll
        for (int q = 1; q < 8; q++) m = fminf(m, sm[q]);
        smin = m;
        g_M[row] = m;
    }
    __syncthreads();
    const float m = smin;
    __half2 hs[4];
    hs[0] = __floats2half2_rn(ex2f((m - a.x) * SCALE_EXP), ex2f((m - a.y) * SCALE_EXP));
    hs[1] = __floats2half2_rn(ex2f((m - a.z) * SCALE_EXP), ex2f((m - a.w) * SCALE_EXP));
    hs[2] = __floats2half2_rn(ex2f((m - b.x) * SCALE_EXP), ex2f((m - b.y) * SCALE_EXP));
    hs[3] = __floats2half2_rn(ex2f((m - b.z) * SCALE_EXP), ex2f((m - b.w) * SCALE_EXP));
    ((uint4*)(g_K + (size_t)row * NDIM))[threadIdx.x] = *(const uint4*)hs;
}

// Persistent iteration kernel: grid (PNSTRIPES, BATCH) = 512 blocks x 256 thr.
// Per iteration: sweep 32-row stripe (8 stages of 4 rows, single-decode t=K*v),
// barrier, combine 32 columns of flattened B*N, barrier.
__global__ void __launch_bounds__(256, 4) sinkhorn_persist() {
    const int stripe = blockIdx.x;                 // 0..63
    const int b = blockIdx.y;                      // 0..7
    const int t = threadIdx.x;
    const int lane = t & 31, w = t >> 5;
    const int bid = b * PNSTRIPES + stripe;        // 0..511
    const int i0 = stripe * PSTRIPE;
    const __half* __restrict__ Kb = g_K + ((size_t)b << (2 * LOGN));

    __shared__ float swp[8][4];
    __shared__ float s_u[4];
    __shared__ float sh[8][32];

    // combine-phase constants (cols [bid*32, bid*32+32) of flattened B*N)
    const int idx0 = bid * 32;
    const int b2 = idx0 >> LOGN;
    const int j0 = idx0 & (NDIM - 1);
    const int cc = t & 31, cp = t >> 5;

    for (int it = 0; it < SINK_ITERS; it++) {
        // ---- sweep phase ----
        const float4* __restrict__ Vb4 = (const float4*)(g_V + (b << LOGN) + 8 * t);
        float4 va = Vb4[0], vb = Vb4[1];
        const float v_own[8] = { va.x, va.y, va.z, va.w, vb.x, vb.y, vb.z, vb.w };
        float acc[8] = { 0, 0, 0, 0, 0, 0, 0, 0 };

#pragma unroll 1
        for (int s = 0; s < PSTRIPE / 4; s++) {
            float tv[4][8];
            float part[4];
#pragma unroll
            for (int r = 0; r < 4; r++) {
                const int i = i0 + s * 4 + r;
                uint4 k = *(const uint4*)(Kb + ((size_t)i << LOGN) + 8 * t);
                float2 f0 = __half22float2(*(__half2*)&k.x);
                float2 f1 = __half22float2(*(__half2*)&k.y);
                float2 f2 = __half22float2(*(__half2*)&k.z);
                float2 f3 = __half22float2(*(__half2*)&k.w);
                tv[r][0] = f0.x * v_own[0]; tv[r][1] = f0.y * v_own[1];
                tv[r][2] = f1.x * v_own[2]; tv[r][3] = f1.y * v_own[3];
                tv[r][4] = f2.x * v_own[4]; tv[r][5] = f2.y * v_own[5];
                tv[r][6] = f3.x * v_own[6]; tv[r][7] = f3.y * v_own[7];
                part[r] = ((tv[r][0] + tv[r][1]) + (tv[r][2] + tv[r][3]))
                        + ((tv[r][4] + tv[r][5]) + (tv[r][6] + tv[r][7]));
            }
#pragma unroll
            for (int r = 0; r < 4; r++) {
                float p = part[r];
#pragma unroll
                for (int o = 16; o; o >>= 1) p += __shfl_xor_sync(0xffffffffu, p, o);
                if (lane == 0) swp[w][r] = p;
            }
            __syncthreads();
            if (t < 4) {
                float ssum = swp[0][t] + swp[1][t] + swp[2][t] + swp[3][t]
                           + swp[4][t] + swp[5][t] + swp[6][t] + swp[7][t];
                float u = 1.0f / ssum;
                s_u[t] = u;
                g_U[(b << LOGN) + i0 + s * 4 + t] = u;
            }
            __syncthreads();
#pragma unroll
            for (int r = 0; r < 4; r++) {
                const float u = s_u[r];
#pragma unroll
                for (int c = 0; c < 8; c++) acc[c] += tv[r][c] * u;
            }
        }
        // acc_j = v_j * partial colsum (A-form partials)
        float4* P = (float4*)(g_part + (((size_t)(b * PNSTRIPES + stripe)) << LOGN) + 8 * t);
        P[0] = make_float4(acc[0], acc[1], acc[2], acc[3]);
        P[1] = make_float4(acc[4], acc[5], acc[6], acc[7]);

        grid_barrier();

        // ---- combine phase: v_new = v_old / sum_stripes A ----
        {
            const float* __restrict__ Pc =
                g_part + (((size_t)b2 * PNSTRIPES) << LOGN) + j0 + cc;
            float ssum = 0.0f;
#pragma unroll
            for (int st = cp; st < PNSTRIPES; st += 8)
                ssum += Pc[(size_t)st << LOGN];
            sh[cp][cc] = ssum;
            __syncthreads();
            if (t < 32) {
                float tsum = sh[0][t] + sh[1][t] + sh[2][t] + sh[3][t]
                           + sh[4][t] + sh[5][t] + sh[6][t] + sh[7][t];
                g_V[idx0 + t] = g_V[idx0 + t] / tsum;
            }
        }

        grid_barrier();
    }
}

// rowpart_i = u_i * sum_j K' v_j D_ij, with D = m_i - EPS_LN2*log2(K').
__global__ void final_row() {
    const int row = blockIdx.x, b = row >> LOGN;
    const uint4* __restrict__ Kr = (const uint4*)(g_K + (size_t)row * NDIM);
    const float4* __restrict__ Vb = (const float4*)(g_V + (b << LOGN));
    const float m = g_M[row];
    uint4 k = Kr[threadIdx.x];
    float4 v0 = Vb[2 * threadIdx.x];
    float4 v1 = Vb[2 * threadIdx.x + 1];
    float2 f0 = __half22float2(*(__half2*)&k.x);
    float2 f1 = __half22float2(*(__half2*)&k.y);
    float2 f2 = __half22float2(*(__half2*)&k.z);
    float2 f3 = __half22float2(*(__half2*)&k.w);
    float acc = 0.0f;
#define TERM(kp, vv) do {                                    \
        float _d = m - EPS_LN2 * lg2f(kp);                   \
        _d = ((kp) > 0.0f) ? _d : 0.0f;                      \
        acc += (kp) * (vv) * _d;                             \
    } while (0)
    TERM(f0.x, v0.x); TERM(f0.y, v0.y); TERM(f1.x, v0.z); TERM(f1.y, v0.w);
    TERM(f2.x, v1.x); TERM(f2.y, v1.y); TERM(f3.x, v1.z); TERM(f3.y, v1.w);
#undef TERM
    float s = block_sum256(acc);
    if (threadIdx.x == 0) g_rowpart[row] = s * g_U[row];
}

__global__ void final_combine(float* __restrict__ out) {
    float s = 0.0f;
    for (int i = threadIdx.x; i < BATCH * NDIM; i += 256) s += g_rowpart[i];
    s = block_sum256(s);
    if (threadIdx.x == 0) out[0] = s / ((float)NDIM * (float)BATCH);
}

extern "C" void kernel_launch(void* const* d_in, const int* in_sizes, int n_in,
                              void* d_out, int out_size) {
    const float* D = (const float*)d_in[0];
    float* out = (float*)d_out;
    (void)in_sizes; (void)n_in; (void)out_size;

    init_v_kernel<<<BATCH * NDIM / 256, 256>>>();
    precompute_kernel<<<BATCH * NDIM, 256>>>(D);
    sinkhorn_persist<<<dim3(PNSTRIPES, BATCH), 256>>>();
    final_row<<<BATCH * NDIM, 256>>>();
    final_combine<<<1, 256>>>(out);
}

// round 14
// speedup vs baseline: 1.2046x; 1.2046x over previous
#include <cuda_runtime.h>
#include <cuda_fp16.h>

// SinkhornLoss B=8, N=2048, EPS=0.1, 20 iters — dense fp16 K' fused sweep.
// R14 (from measured-good R12, persistent R13 reverted):
//  - STRIPE 32 with R12's proven 4-row single-decode stages (partials 4MB).
//  - sweep #20 (sweep_last) also emits W-partials = sum_i tv*u*D, so the
//    67MB final_row pass AND combine #20 vanish: loss_j = sumW_j / sumA_j.

#define BATCH 8
#define NDIM  2048
#define LOGN  11
#define SINK_ITERS 20
#define STRIPE 32
#define NSTRIPES (NDIM / STRIPE)        // 64
#define NBLK     (NSTRIPES * BATCH)     // 512

#define SCALE_EXP 14.426950408889634f   // log2(e)/EPS
#define EPS_LN2   0.06931471805599453f  // EPS*ln(2)

__device__ __half g_K[(size_t)BATCH * NDIM * NDIM];          // 67 MB
__device__ float  g_M[BATCH * NDIM];
__device__ float  g_V[BATCH * NDIM];
__device__ float  g_part[(size_t)BATCH * NSTRIPES * NDIM];   // 4 MB A partials
__device__ float  g_wpart[(size_t)BATCH * NSTRIPES * NDIM];  // 4 MB W partials
__device__ float  g_blockloss[NBLK];

__device__ __forceinline__ float ex2f(float x) {
    float y; asm("ex2.approx.f32 %0, %1;" : "=f"(y) : "f"(x)); return y;
}
__device__ __forceinline__ float lg2f(float x) {
    float y; asm("lg2.approx.f32 %0, %1;" : "=f"(y) : "f"(x)); return y;
}

__global__ void init_v_kernel() {
    g_V[blockIdx.x * 256 + threadIdx.x] = 1.0f;
}

// One block per row: row min, then K'16 = exp2((m - d)*SCALE_EXP).
__global__ void precompute_kernel(const float* __restrict__ D) {
    const int row = blockIdx.x;
    const float4* __restrict__ Dr = (const float4*)(D + (size_t)row * NDIM);
    float4 a = Dr[2 * threadIdx.x];
    float4 b = Dr[2 * threadIdx.x + 1];
    float mn = fminf(fminf(fminf(a.x, a.y), fminf(a.z, a.w)),
                     fminf(fminf(b.x, b.y), fminf(b.z, b.w)));
    __shared__ float sm[8];
    __shared__ float smin;
    const int lane = threadIdx.x & 31, w = threadIdx.x >> 5;
#pragma unroll
    for (int o = 16; o; o >>= 1) mn = fminf(mn, __shfl_xor_sync(0xffffffffu, mn, o));
    if (lane == 0) sm[w] = mn;
    __syncthreads();
    if (threadIdx.x == 0) {
        float m = sm[0];
#pragma unroll
        for (int q = 1; q < 8; q++) m = fminf(m, sm[q]);
        smin = m;
        g_M[row] = m;
    }
    __syncthreads();
    const float m = smin;
    __half2 hs[4];
    hs[0] = __floats2half2_rn(ex2f((m - a.x) * SCALE_EXP), ex2f((m - a.y) * SCALE_EXP));
    hs[1] = __floats2half2_rn(ex2f((m - a.z) * SCALE_EXP), ex2f((m - a.w) * SCALE_EXP));
    hs[2] = __floats2half2_rn(ex2f((m - b.x) * SCALE_EXP), ex2f((m - b.y) * SCALE_EXP));
    hs[3] = __floats2half2_rn(ex2f((m - b.z) * SCALE_EXP), ex2f((m - b.w) * SCALE_EXP));
    ((uint4*)(g_K + (size_t)row * NDIM))[threadIdx.x] = *(const uint4*)hs;
}

// Mid-iteration sweep: grid (NSTRIPES, BATCH) = 512 blocks, 256 threads.
// 32-row stripe = 8 stages of 4 rows; t[r][c] = K*v decoded once per element.
__global__ void __launch_bounds__(256, 4) sweep_mid() {
    const int b = blockIdx.y, stripe = blockIdx.x;
    const int t = threadIdx.x;
    const int lane = t & 31, w = t >> 5;
    const int i0 = stripe * STRIPE;
    const __half* __restrict__ Kb = g_K + ((size_t)b << (2 * LOGN));

    const float4* __restrict__ Vb4 = (const float4*)(g_V + (b << LOGN) + 8 * t);
    float4 va = Vb4[0], vb = Vb4[1];
    const float v_own[8] = { va.x, va.y, va.z, va.w, vb.x, vb.y, vb.z, vb.w };
    float acc[8] = { 0, 0, 0, 0, 0, 0, 0, 0 };

    __shared__ float swp[8][4];
    __shared__ float s_u[4];

#pragma unroll 1
    for (int s = 0; s < STRIPE / 4; s++) {
        float tv[4][8];
        float part[4];
#pragma unroll
        for (int r = 0; r < 4; r++) {
            const int i = i0 + s * 4 + r;
            uint4 k = *(const uint4*)(Kb + ((size_t)i << LOGN) + 8 * t);
            float2 f0 = __half22float2(*(__half2*)&k.x);
            float2 f1 = __half22float2(*(__half2*)&k.y);
            float2 f2 = __half22float2(*(__half2*)&k.z);
            float2 f3 = __half22float2(*(__half2*)&k.w);
            tv[r][0] = f0.x * v_own[0]; tv[r][1] = f0.y * v_own[1];
            tv[r][2] = f1.x * v_own[2]; tv[r][3] = f1.y * v_own[3];
            tv[r][4] = f2.x * v_own[4]; tv[r][5] = f2.y * v_own[5];
            tv[r][6] = f3.x * v_own[6]; tv[r][7] = f3.y * v_own[7];
            part[r] = ((tv[r][0] + tv[r][1]) + (tv[r][2] + tv[r][3]))
                    + ((tv[r][4] + tv[r][5]) + (tv[r][6] + tv[r][7]));
        }
#pragma unroll
        for (int r = 0; r < 4; r++) {
            float p = part[r];
#pragma unroll
            for (int o = 16; o; o >>= 1) p += __shfl_xor_sync(0xffffffffu, p, o);
            if (lane == 0) swp[w][r] = p;
        }
        __syncthreads();
        if (t < 4) {
            float ssum = swp[0][t] + swp[1][t] + swp[2][t] + swp[3][t]
                       + swp[4][t] + swp[5][t] + swp[6][t] + swp[7][t];
            s_u[t] = 1.0f / ssum;
        }
        __syncthreads();
#pragma unroll
        for (int r = 0; r < 4; r++) {
            const float u = s_u[r];
#pragma unroll
            for (int c = 0; c < 8; c++) acc[c] += tv[r][c] * u;
        }
    }
    float4* P = (float4*)(g_part + (((size_t)(b * NSTRIPES + stripe)) << LOGN) + 8 * t);
    P[0] = make_float4(acc[0], acc[1], acc[2], acc[3]);
    P[1] = make_float4(acc[4], acc[5], acc[6], acc[7]);
}

// Last sweep: also accumulates W partials = sum_i tv*u*D with
// D = (m_i + EPS_LN2*lg2(v_own_c)) - EPS_LN2*lg2(tv).  occ 3 (needs ~74 regs).
__global__ void __launch_bounds__(256, 3) sweep_last() {
    const int b = blockIdx.y, stripe = blockIdx.x;
    const int t = threadIdx.x;
    const int lane = t & 31, w = t >> 5;
    const int i0 = stripe * STRIPE;
    const __half* __restrict__ Kb = g_K + ((size_t)b << (2 * LOGN));

    const float4* __restrict__ Vb4 = (const float4*)(g_V + (b << LOGN) + 8 * t);
    float4 va = Vb4[0], vb = Vb4[1];
    const float v_own[8] = { va.x, va.y, va.z, va.w, vb.x, vb.y, vb.z, vb.w };
    float lc[8];
#pragma unroll
    for (int c = 0; c < 8; c++) lc[c] = EPS_LN2 * lg2f(v_own[c]);
    float acc[8] = { 0, 0, 0, 0, 0, 0, 0, 0 };
    float wacc[8] = { 0, 0, 0, 0, 0, 0, 0, 0 };

    __shared__ float swp[8][4];
    __shared__ float s_u[4];
    __shared__ float s_m[4];

#pragma unroll 1
    for (int s = 0; s < STRIPE / 4; s++) {
        float tv[4][8];
        float part[4];
#pragma unroll
        for (int r = 0; r < 4; r++) {
            const int i = i0 + s * 4 + r;
            uint4 k = *(const uint4*)(Kb + ((size_t)i << LOGN) + 8 * t);
            float2 f0 = __half22float2(*(__half2*)&k.x);
            float2 f1 = __half22float2(*(__half2*)&k.y);
            float2 f2 = __half22float2(*(__half2*)&k.z);
            float2 f3 = __half22float2(*(__half2*)&k.w);
            tv[r][0] = f0.x * v_own[0]; tv[r][1] = f0.y * v_own[1];
            tv[r][2] = f1.x * v_own[2]; tv[r][3] = f1.y * v_own[3];
            tv[r][4] = f2.x * v_own[4]; tv[r][5] = f2.y * v_own[5];
            tv[r][6] = f3.x * v_own[6]; tv[r][7] = f3.y * v_own[7];
            part[r] = ((tv[r][0] + tv[r][1]) + (tv[r][2] + tv[r][3]))
                    + ((tv[r][4] + tv[r][5]) + (tv[r][6] + tv[r][7]));
        }
#pragma unroll
        for (int r = 0; r < 4; r++) {
            float p = part[r];
#pragma unroll
            for (int o = 16; o; o >>= 1) p += __shfl_xor_sync(0xffffffffu, p, o);
            if (lane == 0) swp[w][r] = p;
        }
        __syncthreads();
        if (t < 4) {
            float ssum = swp[0][t] + swp[1][t] + swp[2][t] + swp[3][t]
                       + swp[4][t] + swp[5][t] + swp[6][t] + swp[7][t];
            s_u[t] = 1.0f / ssum;
            s_m[t] = g_M[(b << LOGN) + i0 + s * 4 + t];
        }
        __syncthreads();
#pragma unroll
        for (int r = 0; r < 4; r++) {
            const float u = s_u[r];
            const float m = s_m[r];
#pragma unroll
            for (int c = 0; c < 8; c++) {
                float tu = tv[r][c] * u;
                acc[c] += tu;
                float d = (m + lc[c]) - EPS_LN2 * lg2f(tv[r][c]);
                wacc[c] += tu * ((tv[r][c] > 0.0f) ? d : 0.0f);
            }
        }
        __syncthreads();   // protect s_u/s_m reuse (reads above, writes next stage)
    }
    const size_t pbase = (((size_t)(b * NSTRIPES + stripe)) << LOGN) + 8 * t;
    float4* P = (float4*)(g_part + pbase);
    P[0] = make_float4(acc[0], acc[1], acc[2], acc[3]);
    P[1] = make_float4(acc[4], acc[5], acc[6], acc[7]);
    float4* W = (float4*)(g_wpart + pbase);
    W[0] = make_float4(wacc[0], wacc[1], wacc[2], wacc[3]);
    W[1] = make_float4(wacc[4], wacc[5], wacc[6], wacc[7]);
}

// v_new_j = v_old_j / sum_stripes A_j.  512 blocks x 256 thr; 32 cols/block,
// 8 threads per column (each sums NSTRIPES/8 = 8 stripes), shared finish.
__global__ void combine_v() {
    const int bcol = blockIdx.x * 32;
    const int b = bcol >> LOGN;
    const int j0 = bcol & (NDIM - 1);
    const int c = threadIdx.x & 31;
    const int p = threadIdx.x >> 5;
    const float* __restrict__ P =
        g_part + (((size_t)b * NSTRIPES) << LOGN) + j0 + c;
    float s = 0.0f;
#pragma unroll
    for (int st = p; st < NSTRIPES; st += 8) s += P[(size_t)st << LOGN];
    __shared__ float sh[8][32];
    sh[p][c] = s;
    __syncthreads();
    if (threadIdx.x < 32) {
        float tsum = sh[0][threadIdx.x] + sh[1][threadIdx.x]
                   + sh[2][threadIdx.x] + sh[3][threadIdx.x]
                   + sh[4][threadIdx.x] + sh[5][threadIdx.x]
                   + sh[6][threadIdx.x] + sh[7][threadIdx.x];
        g_V[bcol + threadIdx.x] = g_V[bcol + threadIdx.x] / tsum;
    }
}

// loss_j = sumW_j / sumA_j (v_old cancels); block sums 32 columns.
__global__ void finalize() {
    const int bcol = blockIdx.x * 32;
    const int b = bcol >> LOGN;
    const int j0 = bcol & (NDIM - 1);
    const int c = threadIdx.x & 31;
    const int p = threadIdx.x >> 5;
    const size_t base = (((size_t)b * NSTRIPES) << LOGN) + j0 + c;
    float sa = 0.0f, sw = 0.0f;
#pragma unroll
    for (int st = p; st < NSTRIPES; st += 8) {
        sa += g_part [base + ((size_t)st << LOGN)];
        sw += g_wpart[base + ((size_t)st << LOGN)];
    }
    __shared__ float shA[8][32], shW[8][32];
    shA[p][c] = sa; shW[p][c] = sw;
    __syncthreads();
    if (threadIdx.x < 32) {
        float ta = 0.0f, tw = 0.0f;
#pragma unroll
        for (int q = 0; q < 8; q++) { ta += shA[q][threadIdx.x]; tw += shW[q][threadIdx.x]; }
        float lj = tw / ta;
#pragma unroll
        for (int o = 16; o; o >>= 1) lj += __shfl_xor_sync(0xffffffffu, lj, o);
        if (threadIdx.x == 0) g_blockloss[blockIdx.x] = lj;
    }
}

__global__ void reduce_loss(float* __restrict__ out) {
    __shared__ float sm[16];
    const int t = threadIdx.x, lane = t & 31, w = t >> 5;
    float s = g_blockloss[t];            // 512 threads, one value each
#pragma unroll
    for (int o = 16; o; o >>= 1) s += __shfl_xor_sync(0xffffffffu, s, o);
    if (lane == 0) sm[w] = s;
    __syncthreads();
    if (w == 0) {
        s = (lane < 16) ? sm[lane] : 0.0f;
#pragma unroll
        for (int o = 8; o; o >>= 1) s += __shfl_xor_sync(0xffffffffu, s, o);
        if (t == 0) out[0] = s / ((float)NDIM * (float)BATCH);
    }
}

extern "C" void kernel_launch(void* const* d_in, const int* in_sizes, int n_in,
                              void* d_out, int out_size) {
    const float* D = (const float*)d_in[0];
    float* out = (float*)d_out;
    (void)in_sizes; (void)n_in; (void)out_size;

    init_v_kernel<<<BATCH * NDIM / 256, 256>>>();
    precompute_kernel<<<BATCH * NDIM, 256>>>(D);
    for (int t = 0; t < SINK_ITERS - 1; t++) {
        sweep_mid<<<dim3(NSTRIPES, BATCH), 256>>>();
        combine_v<<<BATCH * NDIM / 32, 256>>>();
    }
    sweep_last<<<dim3(NSTRIPES, BATCH), 256>>>();
    finalize<<<BATCH * NDIM / 32, 256>>>();
    reduce_loss<<<1, 512>>>(out);
}

// round 16
// speedup vs baseline: 1.2054x; 1.0007x over previous
#include <cuda_runtime.h>
#include <cuda_fp16.h>

// SinkhornLoss B=8, N=2048, EPS=0.1, 20 iters — dense fp16 K' fused sweep.
// R15: revert sweep to R12's measured-best stripe-16 shape (6.8us vs 9.1 at
// stripe 32), keep R14's W-fused last sweep, add PDL (programmatic dependent
// launch) so each kernel's CTAs fill SMs while the predecessor drains.

#define BATCH 8
#define NDIM  2048
#define LOGN  11
#define SINK_ITERS 20
#define STRIPE 16
#define NSTRIPES (NDIM / STRIPE)        // 128

#define SCALE_EXP 14.426950408889634f   // log2(e)/EPS
#define EPS_LN2   0.06931471805599453f  // EPS*ln(2)

__device__ __half g_K[(size_t)BATCH * NDIM * NDIM];          // 67 MB
__device__ float  g_M[BATCH * NDIM];
__device__ float  g_V[BATCH * NDIM];
__device__ float  g_part[(size_t)BATCH * NSTRIPES * NDIM];   // 8 MB A partials
__device__ float  g_wpart[(size_t)BATCH * NSTRIPES * NDIM];  // 8 MB W partials
__device__ float  g_blockloss[BATCH * NDIM / 32];

__device__ __forceinline__ float ex2f(float x) {
    float y; asm("ex2.approx.f32 %0, %1;" : "=f"(y) : "f"(x)); return y;
}
__device__ __forceinline__ float lg2f(float x) {
    float y; asm("lg2.approx.f32 %0, %1;" : "=f"(y) : "f"(x)); return y;
}
__device__ __forceinline__ void pdl_trigger() {
    asm volatile("griddepcontrol.launch_dependents;");
}
__device__ __forceinline__ void pdl_wait() {
    asm volatile("griddepcontrol.wait;" ::: "memory");
}

// One block per row: row min, K'16 = exp2((m-d)*SCALE_EXP), V init.
__global__ void precompute_kernel(const float* __restrict__ D) {
    pdl_trigger();
    const int row = blockIdx.x;
    const float4* __restrict__ Dr = (const float4*)(D + (size_t)row * NDIM);
    float4 a = Dr[2 * threadIdx.x];
    float4 b = Dr[2 * threadIdx.x + 1];
    float mn = fminf(fminf(fminf(a.x, a.y), fminf(a.z, a.w)),
                     fminf(fminf(b.x, b.y), fminf(b.z, b.w)));
    __shared__ float sm[8];
    __shared__ float smin;
    const int lane = threadIdx.x & 31, w = threadIdx.x >> 5;
#pragma unroll
    for (int o = 16; o; o >>= 1) mn = fminf(mn, __shfl_xor_sync(0xffffffffu, mn, o));
    if (lane == 0) sm[w] = mn;
    __syncthreads();
    if (threadIdx.x == 0) {
        float m = sm[0];
#pragma unroll
        for (int q = 1; q < 8; q++) m = fminf(m, sm[q]);
        smin = m;
        g_M[row] = m;
        g_V[row] = 1.0f;
    }
    __syncthreads();
    const float m = smin;
    __half2 hs[4];
    hs[0] = __floats2half2_rn(ex2f((m - a.x) * SCALE_EXP), ex2f((m - a.y) * SCALE_EXP));
    hs[1] = __floats2half2_rn(ex2f((m - a.z) * SCALE_EXP), ex2f((m - a.w) * SCALE_EXP));
    hs[2] = __floats2half2_rn(ex2f((m - b.x) * SCALE_EXP), ex2f((m - b.y) * SCALE_EXP));
    hs[3] = __floats2half2_rn(ex2f((m - b.z) * SCALE_EXP), ex2f((m - b.w) * SCALE_EXP));
    ((uint4*)(g_K + (size_t)row * NDIM))[threadIdx.x] = *(const uint4*)hs;
}

// Mid sweep (R12-exact): grid (NSTRIPES, BATCH) = 1024 blocks, 256 threads.
// 16-row stripe = 4 stages of 4 rows; tv[r][c] = K*v decoded once per element.
__global__ void __launch_bounds__(256, 4) sweep_mid() {
    pdl_trigger();
    const int b = blockIdx.y, stripe = blockIdx.x;
    const int t = threadIdx.x;
    const int lane = t & 31, w = t >> 5;
    const int i0 = stripe * STRIPE;
    const __half* __restrict__ Kb = g_K + ((size_t)b << (2 * LOGN));

    pdl_wait();
    const float4* __restrict__ Vb4 = (const float4*)(g_V + (b << LOGN) + 8 * t);
    float4 va = Vb4[0], vb = Vb4[1];
    const float v_own[8] = { va.x, va.y, va.z, va.w, vb.x, vb.y, vb.z, vb.w };
    float acc[8] = { 0, 0, 0, 0, 0, 0, 0, 0 };

    __shared__ float swp[8][4];
    __shared__ float s_u[4];

#pragma unroll
    for (int s = 0; s < STRIPE / 4; s++) {
        float tv[4][8];
        float part[4];
#pragma unroll
        for (int r = 0; r < 4; r++) {
            const int i = i0 + s * 4 + r;
            uint4 k = *(const uint4*)(Kb + ((size_t)i << LOGN) + 8 * t);
            float2 f0 = __half22float2(*(__half2*)&k.x);
            float2 f1 = __half22float2(*(__half2*)&k.y);
            float2 f2 = __half22float2(*(__half2*)&k.z);
            float2 f3 = __half22float2(*(__half2*)&k.w);
            tv[r][0] = f0.x * v_own[0]; tv[r][1] = f0.y * v_own[1];
            tv[r][2] = f1.x * v_own[2]; tv[r][3] = f1.y * v_own[3];
            tv[r][4] = f2.x * v_own[4]; tv[r][5] = f2.y * v_own[5];
            tv[r][6] = f3.x * v_own[6]; tv[r][7] = f3.y * v_own[7];
            part[r] = ((tv[r][0] + tv[r][1]) + (tv[r][2] + tv[r][3]))
                    + ((tv[r][4] + tv[r][5]) + (tv[r][6] + tv[r][7]));
        }
#pragma unroll
        for (int r = 0; r < 4; r++) {
            float p = part[r];
#pragma unroll
            for (int o = 16; o; o >>= 1) p += __shfl_xor_sync(0xffffffffu, p, o);
            if (lane == 0) swp[w][r] = p;
        }
        __syncthreads();
        if (t < 4) {
            float ssum = swp[0][t] + swp[1][t] + swp[2][t] + swp[3][t]
                       + swp[4][t] + swp[5][t] + swp[6][t] + swp[7][t];
            s_u[t] = 1.0f / ssum;
        }
        __syncthreads();
#pragma unroll
        for (int r = 0; r < 4; r++) {
            const float u = s_u[r];
#pragma unroll
            for (int c = 0; c < 8; c++) acc[c] += tv[r][c] * u;
        }
    }
    float4* P = (float4*)(g_part + (((size_t)(b * NSTRIPES + stripe)) << LOGN) + 8 * t);
    P[0] = make_float4(acc[0], acc[1], acc[2], acc[3]);
    P[1] = make_float4(acc[4], acc[5], acc[6], acc[7]);
}

// Last sweep: W partials too; D = (m_i + EPS_LN2*lg2(v_own)) - EPS_LN2*lg2(tv).
__global__ void __launch_bounds__(256, 3) sweep_last() {
    pdl_trigger();
    const int b = blockIdx.y, stripe = blockIdx.x;
    const int t = threadIdx.x;
    const int lane = t & 31, w = t >> 5;
    const int i0 = stripe * STRIPE;
    const __half* __restrict__ Kb = g_K + ((size_t)b << (2 * LOGN));

    pdl_wait();
    const float4* __restrict__ Vb4 = (const float4*)(g_V + (b << LOGN) + 8 * t);
    float4 va = Vb4[0], vb = Vb4[1];
    const float v_own[8] = { va.x, va.y, va.z, va.w, vb.x, vb.y, vb.z, vb.w };
    float lc[8];
#pragma unroll
    for (int c = 0; c < 8; c++) lc[c] = EPS_LN2 * lg2f(v_own[c]);
    float acc[8] = { 0, 0, 0, 0, 0, 0, 0, 0 };
    float wacc[8] = { 0, 0, 0, 0, 0, 0, 0, 0 };

    __shared__ float swp[8][4];
    __shared__ float s_u[4];
    __shared__ float s_m[4];

#pragma unroll 1
    for (int s = 0; s < STRIPE / 4; s++) {
        float tv[4][8];
        float part[4];
#pragma unroll
        for (int r = 0; r < 4; r++) {
            const int i = i0 + s * 4 + r;
            uint4 k = *(const uint4*)(Kb + ((size_t)i << LOGN) + 8 * t);
            float2 f0 = __half22float2(*(__half2*)&k.x);
            float2 f1 = __half22float2(*(__half2*)&k.y);
            float2 f2 = __half22float2(*(__half2*)&k.z);
            float2 f3 = __half22float2(*(__half2*)&k.w);
            tv[r][0] = f0.x * v_own[0]; tv[r][1] = f0.y * v_own[1];
            tv[r][2] = f1.x * v_own[2]; tv[r][3] = f1.y * v_own[3];
            tv[r][4] = f2.x * v_own[4]; tv[r][5] = f2.y * v_own[5];
            tv[r][6] = f3.x * v_own[6]; tv[r][7] = f3.y * v_own[7];
            part[r] = ((tv[r][0] + tv[r][1]) + (tv[r][2] + tv[r][3]))
                    + ((tv[r][4] + tv[r][5]) + (tv[r][6] + tv[r][7]));
        }
#pragma unroll
        for (int r = 0; r < 4; r++) {
            float p = part[r];
#pragma unroll
            for (int o = 16; o; o >>= 1) p += __shfl_xor_sync(0xffffffffu, p, o);
            if (lane == 0) swp[w][r] = p;
        }
        __syncthreads();
        if (t < 4) {
            float ssum = swp[0][t] + swp[1][t] + swp[2][t] + swp[3][t]
                       + swp[4][t] + swp[5][t] + swp[6][t] + swp[7][t];
            s_u[t] = 1.0f / ssum;
            s_m[t] = g_M[(b << LOGN) + i0 + s * 4 + t];
        }
        __syncthreads();
#pragma unroll
        for (int r = 0; r < 4; r++) {
            const float u = s_u[r];
            const float m = s_m[r];
#pragma unroll
            for (int c = 0; c < 8; c++) {
                float tu = tv[r][c] * u;
                acc[c] += tu;
                float d = (m + lc[c]) - EPS_LN2 * lg2f(tv[r][c]);
                wacc[c] += tu * ((tv[r][c] > 0.0f) ? d : 0.0f);
            }
        }
        __syncthreads();
    }
    const size_t pbase = (((size_t)(b * NSTRIPES + stripe)) << LOGN) + 8 * t;
    float4* P = (float4*)(g_part + pbase);
    P[0] = make_float4(acc[0], acc[1], acc[2], acc[3]);
    P[1] = make_float4(acc[4], acc[5], acc[6], acc[7]);
    float4* W = (float4*)(g_wpart + pbase);
    W[0] = make_float4(wacc[0], wacc[1], wacc[2], wacc[3]);
    W[1] = make_float4(wacc[4], wacc[5], wacc[6], wacc[7]);
}

// v_new_j = v_old_j / sum_stripes A_j. 512 blocks x 256 thr; 32 cols/block.
__global__ void combine_v() {
    pdl_trigger();
    const int bcol = blockIdx.x * 32;
    const int b = bcol >> LOGN;
    const int j0 = bcol & (NDIM - 1);
    const int c = threadIdx.x & 31;
    const int p = threadIdx.x >> 5;
    pdl_wait();
    const float* __restrict__ P =
        g_part + (((size_t)b * NSTRIPES) << LOGN) + j0 + c;
    float s = 0.0f;
#pragma unroll
    for (int st = p; st < NSTRIPES; st += 8) s += P[(size_t)st << LOGN];
    __shared__ float sh[8][32];
    sh[p][c] = s;
    __syncthreads();
    if (threadIdx.x < 32) {
        float tsum = sh[0][threadIdx.x] + sh[1][threadIdx.x]
                   + sh[2][threadIdx.x] + sh[3][threadIdx.x]
                   + sh[4][threadIdx.x] + sh[5][threadIdx.x]
                   + sh[6][threadIdx.x] + sh[7][threadIdx.x];
        g_V[bcol + threadIdx.x] = g_V[bcol + threadIdx.x] / tsum;
    }
}

// loss_j = sumW_j / sumA_j (v cancels); block covers 32 columns.
__global__ void finalize() {
    pdl_trigger();
    const int bcol = blockIdx.x * 32;
    const int b = bcol >> LOGN;
    const int j0 = bcol & (NDIM - 1);
    const int c = threadIdx.x & 31;
    const int p = threadIdx.x >> 5;
    pdl_wait();
    const size_t base = (((size_t)b * NSTRIPES) << LOGN) + j0 + c;
    float sa = 0.0f, sw = 0.0f;
#pragma unroll
    for (int st = p; st < NSTRIPES; st += 8) {
        sa += g_part [base + ((size_t)st << LOGN)];
        sw += g_wpart[base + ((size_t)st << LOGN)];
    }
    __shared__ float shA[8][32], shW[8][32];
    shA[p][c] = sa; shW[p][c] = sw;
    __syncthreads();
    if (threadIdx.x < 32) {
        float ta = 0.0f, tw = 0.0f;
#pragma unroll
        for (int q = 0; q < 8; q++) { ta += shA[q][threadIdx.x]; tw += shW[q][threadIdx.x]; }
        float lj = tw / ta;
#pragma unroll
        for (int o = 16; o; o >>= 1) lj += __shfl_xor_sync(0xffffffffu, lj, o);
        if (threadIdx.x == 0) g_blockloss[blockIdx.x] = lj;
    }
}

__global__ void reduce_loss(float* __restrict__ out) {
    pdl_trigger();
    __shared__ float sm[16];
    const int t = threadIdx.x, lane = t & 31, w = t >> 5;
    pdl_wait();
    float s = g_blockloss[t];            // 512 values, one per thread
#pragma unroll
    for (int o = 16; o; o >>= 1) s += __shfl_xor_sync(0xffffffffu, s, o);
    if (lane == 0) sm[w] = s;
    __syncthreads();
    if (w == 0) {
        s = (lane < 16) ? sm[lane] : 0.0f;
#pragma unroll
        for (int o = 8; o; o >>= 1) s += __shfl_xor_sync(0xffffffffu, s, o);
        if (t == 0) out[0] = s / ((float)NDIM * (float)BATCH);
    }
}

// PDL launch helper: secondary may begin scheduling while predecessor drains.
template <typename F, typename... Args>
static inline void launch_pdl(F f, dim3 grid, dim3 block, Args... args) {
    cudaLaunchConfig_t cfg = {};
    cfg.gridDim = grid;
    cfg.blockDim = block;
    cfg.dynamicSmemBytes = 0;
    cfg.stream = 0;
    cudaLaunchAttribute at[1];
    at[0].id = cudaLaunchAttributeProgrammaticStreamSerialization;
    at[0].val.programmaticStreamSerializationAllowed = 1;
    cfg.attrs = at;
    cfg.numAttrs = 1;
    cudaLaunchKernelEx(&cfg, f, args...);
}

extern "C" void kernel_launch(void* const* d_in, const int* in_sizes, int n_in,
                              void* d_out, int out_size) {
    const float* D = (const float*)d_in[0];
    float* out = (float*)d_out;
    (void)in_sizes; (void)n_in; (void)out_size;

    precompute_kernel<<<BATCH * NDIM, 256>>>(D);
    for (int t = 0; t < SINK_ITERS - 1; t++) {
        launch_pdl(sweep_mid, dim3(NSTRIPES, BATCH), dim3(256));
        launch_pdl(combine_v, dim3(BATCH * NDIM / 32), dim3(256));
    }
    launch_pdl(sweep_last, dim3(NSTRIPES, BATCH), dim3(256));
    launch_pdl(finalize, dim3(BATCH * NDIM / 32), dim3(256));
    launch_pdl(reduce_loss, dim3(1), dim3(512), out);
}

// round 17
// speedup vs baseline: 1.3054x; 1.0830x over previous
#include <cuda_runtime.h>
#include <cuda_fp16.h>
#include <cuda_fp8.h>

// SinkhornLoss B=8, N=2048, EPS=0.1, 20 iters — FP8(e4m3) K' fused sweep.
// R17: K'' = 448 * 2^((m-D)*log2e/EPS) stored e4m3 (33.5 MB — half of fp16).
// Scale 448 cancels in u/A/W. Sweep decodes e4m3->half2->float2 (compute
// headroom measured ~2x). sweep_last reconstructs D with +lg2(448) shift.

#define BATCH 8
#define NDIM  2048
#define LOGN  11
#define SINK_ITERS 20
#define STRIPE 16
#define NSTRIPES (NDIM / STRIPE)        // 128

#define SCALE_EXP 14.426950408889634f   // log2(e)/EPS
#define EPS_LN2   0.06931471805599453f  // EPS*ln(2)
#define LOG2_448  8.807354922057604f    // lg2(448)
#define FP8_SCALE 448.0f

__device__ unsigned char g_K8[(size_t)BATCH * NDIM * NDIM];  // 33.5 MB e4m3
__device__ float  g_M[BATCH * NDIM];
__device__ float  g_V[BATCH * NDIM];
__device__ float  g_part[(size_t)BATCH * NSTRIPES * NDIM];   // 8 MB A partials
__device__ float  g_wpart[(size_t)BATCH * NSTRIPES * NDIM];  // 8 MB W partials
__device__ float  g_blockloss[BATCH * NDIM / 32];

__device__ __forceinline__ float ex2f(float x) {
    float y; asm("ex2.approx.f32 %0, %1;" : "=f"(y) : "f"(x)); return y;
}
__device__ __forceinline__ float lg2f(float x) {
    float y; asm("lg2.approx.f32 %0, %1;" : "=f"(y) : "f"(x)); return y;
}
__device__ __forceinline__ void pdl_trigger() {
    asm volatile("griddepcontrol.launch_dependents;");
}
__device__ __forceinline__ void pdl_wait() {
    asm volatile("griddepcontrol.wait;" ::: "memory");
}
// decode 2 packed e4m3 -> float2
__device__ __forceinline__ float2 fp8x2_to_f2(unsigned short p) {
    __half2_raw h = __nv_cvt_fp8x2_to_halfraw2((__nv_fp8x2_storage_t)p, __NV_E4M3);
    return __half22float2(*(__half2*)&h);
}

// One block per row: row min, K8 = e4m3(448 * exp2((m-d)*SCALE_EXP)), V init.
__global__ void precompute_kernel(const float* __restrict__ D) {
    pdl_trigger();
    const int row = blockIdx.x;
    const float4* __restrict__ Dr = (const float4*)(D + (size_t)row * NDIM);
    float4 a = Dr[2 * threadIdx.x];
    float4 b = Dr[2 * threadIdx.x + 1];
    float mn = fminf(fminf(fminf(a.x, a.y), fminf(a.z, a.w)),
                     fminf(fminf(b.x, b.y), fminf(b.z, b.w)));
    __shared__ float sm[8];
    __shared__ float smin;
    const int lane = threadIdx.x & 31, w = threadIdx.x >> 5;
#pragma unroll
    for (int o = 16; o; o >>= 1) mn = fminf(mn, __shfl_xor_sync(0xffffffffu, mn, o));
    if (lane == 0) sm[w] = mn;
    __syncthreads();
    if (threadIdx.x == 0) {
        float m = sm[0];
#pragma unroll
        for (int q = 1; q < 8; q++) m = fminf(m, sm[q]);
        smin = m;
        g_M[row] = m;
        g_V[row] = 1.0f;
    }
    __syncthreads();
    const float m = smin;
    float e[8];
    e[0] = ex2f((m - a.x) * SCALE_EXP) * FP8_SCALE;
    e[1] = ex2f((m - a.y) * SCALE_EXP) * FP8_SCALE;
    e[2] = ex2f((m - a.z) * SCALE_EXP) * FP8_SCALE;
    e[3] = ex2f((m - a.w) * SCALE_EXP) * FP8_SCALE;
    e[4] = ex2f((m - b.x) * SCALE_EXP) * FP8_SCALE;
    e[5] = ex2f((m - b.y) * SCALE_EXP) * FP8_SCALE;
    e[6] = ex2f((m - b.z) * SCALE_EXP) * FP8_SCALE;
    e[7] = ex2f((m - b.w) * SCALE_EXP) * FP8_SCALE;
    unsigned short p0 = __nv_cvt_float2_to_fp8x2(make_float2(e[0], e[1]), __NV_SATFINITE, __NV_E4M3);
    unsigned short p1 = __nv_cvt_float2_to_fp8x2(make_float2(e[2], e[3]), __NV_SATFINITE, __NV_E4M3);
    unsigned short p2 = __nv_cvt_float2_to_fp8x2(make_float2(e[4], e[5]), __NV_SATFINITE, __NV_E4M3);
    unsigned short p3 = __nv_cvt_float2_to_fp8x2(make_float2(e[6], e[7]), __NV_SATFINITE, __NV_E4M3);
    uint2 pk;
    pk.x = (unsigned)p0 | ((unsigned)p1 << 16);
    pk.y = (unsigned)p2 | ((unsigned)p3 << 16);
    *(uint2*)(g_K8 + (size_t)row * NDIM + 8 * threadIdx.x) = pk;
}

// Mid sweep: grid (NSTRIPES, BATCH) = 1024 blocks, 256 threads.
// 16-row stripe = 4 stages of 4 rows; tv[r][c] = K*v decoded once per element.
__global__ void __launch_bounds__(256, 4) sweep_mid() {
    pdl_trigger();
    const int b = blockIdx.y, stripe = blockIdx.x;
    const int t = threadIdx.x;
    const int lane = t & 31, w = t >> 5;
    const int i0 = stripe * STRIPE;
    const unsigned char* __restrict__ Kb = g_K8 + ((size_t)b << (2 * LOGN));

    pdl_wait();
    const float4* __restrict__ Vb4 = (const float4*)(g_V + (b << LOGN) + 8 * t);
    float4 va = Vb4[0], vb = Vb4[1];
    const float v_own[8] = { va.x, va.y, va.z, va.w, vb.x, vb.y, vb.z, vb.w };
    float acc[8] = { 0, 0, 0, 0, 0, 0, 0, 0 };

    __shared__ float swp[8][4];
    __shared__ float s_u[4];

#pragma unroll
    for (int s = 0; s < STRIPE / 4; s++) {
        float tv[4][8];
        float part[4];
#pragma unroll
        for (int r = 0; r < 4; r++) {
            const int i = i0 + s * 4 + r;
            uint2 k = *(const uint2*)(Kb + ((size_t)i << LOGN) + 8 * t);
            float2 f0 = fp8x2_to_f2((unsigned short)(k.x & 0xffffu));
            float2 f1 = fp8x2_to_f2((unsigned short)(k.x >> 16));
            float2 f2 = fp8x2_to_f2((unsigned short)(k.y & 0xffffu));
            float2 f3 = fp8x2_to_f2((unsigned short)(k.y >> 16));
            tv[r][0] = f0.x * v_own[0]; tv[r][1] = f0.y * v_own[1];
            tv[r][2] = f1.x * v_own[2]; tv[r][3] = f1.y * v_own[3];
            tv[r][4] = f2.x * v_own[4]; tv[r][5] = f2.y * v_own[5];
            tv[r][6] = f3.x * v_own[6]; tv[r][7] = f3.y * v_own[7];
            part[r] = ((tv[r][0] + tv[r][1]) + (tv[r][2] + tv[r][3]))
                    + ((tv[r][4] + tv[r][5]) + (tv[r][6] + tv[r][7]));
        }
#pragma unroll
        for (int r = 0; r < 4; r++) {
            float p = part[r];
#pragma unroll
            for (int o = 16; o; o >>= 1) p += __shfl_xor_sync(0xffffffffu, p, o);
            if (lane == 0) swp[w][r] = p;
        }
        __syncthreads();
        if (t < 4) {
            float ssum = swp[0][t] + swp[1][t] + swp[2][t] + swp[3][t]
                       + swp[4][t] + swp[5][t] + swp[6][t] + swp[7][t];
            s_u[t] = 1.0f / ssum;
        }
        __syncthreads();
#pragma unroll
        for (int r = 0; r < 4; r++) {
            const float u = s_u[r];
#pragma unroll
            for (int c = 0; c < 8; c++) acc[c] += tv[r][c] * u;
        }
    }
    float4* P = (float4*)(g_part + (((size_t)(b * NSTRIPES + stripe)) << LOGN) + 8 * t);
    P[0] = make_float4(acc[0], acc[1], acc[2], acc[3]);
    P[1] = make_float4(acc[4], acc[5], acc[6], acc[7]);
}

// Last sweep: W partials; D = (m_i + EPS_LN2*(lg2(v_own)+LOG2_448)) - EPS_LN2*lg2(tv).
__global__ void __launch_bounds__(256, 3) sweep_last() {
    pdl_trigger();
    const int b = blockIdx.y, stripe = blockIdx.x;
    const int t = threadIdx.x;
    const int lane = t & 31, w = t >> 5;
    const int i0 = stripe * STRIPE;
    const unsigned char* __restrict__ Kb = g_K8 + ((size_t)b << (2 * LOGN));

    pdl_wait();
    const float4* __restrict__ Vb4 = (const float4*)(g_V + (b << LOGN) + 8 * t);
    float4 va = Vb4[0], vb = Vb4[1];
    const float v_own[8] = { va.x, va.y, va.z, va.w, vb.x, vb.y, vb.z, vb.w };
    float lc[8];
#pragma unroll
    for (int c = 0; c < 8; c++) lc[c] = EPS_LN2 * (lg2f(v_own[c]) + LOG2_448);
    float acc[8] = { 0, 0, 0, 0, 0, 0, 0, 0 };
    float wacc[8] = { 0, 0, 0, 0, 0, 0, 0, 0 };

    __shared__ float swp[8][4];
    __shared__ float s_u[4];
    __shared__ float s_m[4];

#pragma unroll 1
    for (int s = 0; s < STRIPE / 4; s++) {
        float tv[4][8];
        float part[4];
#pragma unroll
        for (int r = 0; r < 4; r++) {
            const int i = i0 + s * 4 + r;
            uint2 k = *(const uint2*)(Kb + ((size_t)i << LOGN) + 8 * t);
            float2 f0 = fp8x2_to_f2((unsigned short)(k.x & 0xffffu));
            float2 f1 = fp8x2_to_f2((unsigned short)(k.x >> 16));
            float2 f2 = fp8x2_to_f2((unsigned short)(k.y & 0xffffu));
            float2 f3 = fp8x2_to_f2((unsigned short)(k.y >> 16));
            tv[r][0] = f0.x * v_own[0]; tv[r][1] = f0.y * v_own[1];
            tv[r][2] = f1.x * v_own[2]; tv[r][3] = f1.y * v_own[3];
            tv[r][4] = f2.x * v_own[4]; tv[r][5] = f2.y * v_own[5];
            tv[r][6] = f3.x * v_own[6]; tv[r][7] = f3.y * v_own[7];
            part[r] = ((tv[r][0] + tv[r][1]) + (tv[r][2] + tv[r][3]))
                    + ((tv[r][4] + tv[r][5]) + (tv[r][6] + tv[r][7]));
        }
#pragma unroll
        for (int r = 0; r < 4; r++) {
            float p = part[r];
#pragma unroll
            for (int o = 16; o; o >>= 1) p += __shfl_xor_sync(0xffffffffu, p, o);
            if (lane == 0) swp[w][r] = p;
        }
        __syncthreads();
        if (t < 4) {
            float ssum = swp[0][t] + swp[1][t] + swp[2][t] + swp[3][t]
                       + swp[4][t] + swp[5][t] + swp[6][t] + swp[7][t];
            s_u[t] = 1.0f / ssum;
            s_m[t] = g_M[(b << LOGN) + i0 + s * 4 + t];
        }
        __syncthreads();
#pragma unroll
        for (int r = 0; r < 4; r++) {
            const float u = s_u[r];
            const float m = s_m[r];
#pragma unroll
            for (int c = 0; c < 8; c++) {
                float tu = tv[r][c] * u;
                acc[c] += tu;
                float d = (m + lc[c]) - EPS_LN2 * lg2f(tv[r][c]);
                wacc[c] += tu * ((tv[r][c] > 0.0f) ? d : 0.0f);
            }
        }
        __syncthreads();
    }
    const size_t pbase = (((size_t)(b * NSTRIPES + stripe)) << LOGN) + 8 * t;
    float4* P = (float4*)(g_part + pbase);
    P[0] = make_float4(acc[0], acc[1], acc[2], acc[3]);
    P[1] = make_float4(acc[4], acc[5], acc[6], acc[7]);
    float4* W = (float4*)(g_wpart + pbase);
    W[0] = make_float4(wacc[0], wacc[1], wacc[2], wacc[3]);
    W[1] = make_float4(wacc[4], wacc[5], wacc[6], wacc[7]);
}

// v_new_j = v_old_j / sum_stripes A_j. 512 blocks x 256 thr; 32 cols/block.
__global__ void combine_v() {
    pdl_trigger();
    const int bcol = blockIdx.x * 32;
    const int b = bcol >> LOGN;
    const int j0 = bcol & (NDIM - 1);
    const int c = threadIdx.x & 31;
    const int p = threadIdx.x >> 5;
    pdl_wait();
    const float* __restrict__ P =
        g_part + (((size_t)b * NSTRIPES) << LOGN) + j0 + c;
    float s = 0.0f;
#pragma unroll
    for (int st = p; st < NSTRIPES; st += 8) s += P[(size_t)st << LOGN];
    __shared__ float sh[8][32];
    sh[p][c] = s;
    __syncthreads();
    if (threadIdx.x < 32) {
        float tsum = sh[0][threadIdx.x] + sh[1][threadIdx.x]
                   + sh[2][threadIdx.x] + sh[3][threadIdx.x]
                   + sh[4][threadIdx.x] + sh[5][threadIdx.x]
                   + sh[6][threadIdx.x] + sh[7][threadIdx.x];
        g_V[bcol + threadIdx.x] = g_V[bcol + threadIdx.x] / tsum;
    }
}

// loss_j = sumW_j / sumA_j (v cancels); block covers 32 columns.
__global__ void finalize() {
    pdl_trigger();
    const int bcol = blockIdx.x * 32;
    const int b = bcol >> LOGN;
    const int j0 = bcol & (NDIM - 1);
    const int c = threadIdx.x & 31;
    const int p = threadIdx.x >> 5;
    pdl_wait();
    const size_t base = (((size_t)b * NSTRIPES) << LOGN) + j0 + c;
    float sa = 0.0f, sw = 0.0f;
#pragma unroll
    for (int st = p; st < NSTRIPES; st += 8) {
        sa += g_part [base + ((size_t)st << LOGN)];
        sw += g_wpart[base + ((size_t)st << LOGN)];
    }
    __shared__ float shA[8][32], shW[8][32];
    shA[p][c] = sa; shW[p][c] = sw;
    __syncthreads();
    if (threadIdx.x < 32) {
        float ta = 0.0f, tw = 0.0f;
#pragma unroll
        for (int q = 0; q < 8; q++) { ta += shA[q][threadIdx.x]; tw += shW[q][threadIdx.x]; }
        float lj = tw / ta;
#pragma unroll
        for (int o = 16; o; o >>= 1) lj += __shfl_xor_sync(0xffffffffu, lj, o);
        if (threadIdx.x == 0) g_blockloss[blockIdx.x] = lj;
    }
}

__global__ void reduce_loss(float* __restrict__ out) {
    pdl_trigger();
    __shared__ float sm[16];
    const int t = threadIdx.x, lane = t & 31, w = t >> 5;
    pdl_wait();
    float s = g_blockloss[t];            // 512 values, one per thread
#pragma unroll
    for (int o = 16; o; o >>= 1) s += __shfl_xor_sync(0xffffffffu, s, o);
    if (lane == 0) sm[w] = s;
    __syncthreads();
    if (w == 0) {
        s = (lane < 16) ? sm[lane] : 0.0f;
#pragma unroll
        for (int o = 8; o; o >>= 1) s += __shfl_xor_sync(0xffffffffu, s, o);
        if (t == 0) out[0] = s / ((float)NDIM * (float)BATCH);
    }
}

template <typename F, typename... Args>
static inline void launch_pdl(F f, dim3 grid, dim3 block, Args... args) {
    cudaLaunchConfig_t cfg = {};
    cfg.gridDim = grid;
    cfg.blockDim = block;
    cfg.dynamicSmemBytes = 0;
    cfg.stream = 0;
    cudaLaunchAttribute at[1];
    at[0].id = cudaLaunchAttributeProgrammaticStreamSerialization;
    at[0].val.programmaticStreamSerializationAllowed = 1;
    cfg.attrs = at;
    cfg.numAttrs = 1;
    cudaLaunchKernelEx(&cfg, f, args...);
}

extern "C" void kernel_launch(void* const* d_in, const int* in_sizes, int n_in,
                              void* d_out, int out_size) {
    const float* D = (const float*)d_in[0];
    float* out = (float*)d_out;
    (void)in_sizes; (void)n_in; (void)out_size;

    precompute_kernel<<<BATCH * NDIM, 256>>>(D);
    for (int t = 0; t < SINK_ITERS - 1; t++) {
        launch_pdl(sweep_mid, dim3(NSTRIPES, BATCH), dim3(256));
        launch_pdl(combine_v, dim3(BATCH * NDIM / 32), dim3(256));
    }
    launch_pdl(sweep_last, dim3(NSTRIPES, BATCH), dim3(256));
    launch_pdl(finalize, dim3(BATCH * NDIM / 32), dim3(256));
    launch_pdl(reduce_loss, dim3(1), dim3(512), out);
}